// round 5
// baseline (speedup 1.0000x reference)
#include <cuda_runtime.h>
#include <cstdint>

#define NB     64
#define NCAND  22743      // 3*(19^2) + 3*(38^2) + 3*(76^2)
#define MCAND  256
#define NEGF   (-1e9f)

// level boundaries in flat candidate index space
// L0: [0,1083) G=19 stride=32 ; L1: [1083,5415) G=38 stride=16 ; L2: [5415,22743) G=76 stride=8

__constant__ float c_anchors[3][3][2] = {
  {{116.f, 90.f},{156.f,198.f},{373.f,326.f}},
  {{ 30.f, 61.f},{ 62.f, 45.f},{ 59.f,119.f}},
  {{ 10.f, 13.f},{ 16.f, 30.f},{ 33.f, 23.f}}
};

__device__ uint32_t g_keys[(size_t)NB * NCAND];  // order-preserving keys of masked scores
__device__ int      g_sel [(size_t)NB * MCAND];  // selected candidate indices per image

__device__ __forceinline__ uint32_t fkey(float f) {
  uint32_t u = __float_as_uint(f);
  return (u & 0x80000000u) ? ~u : (u | 0x80000000u);
}

struct Cand { float x1, y1, x2, y2, val; int cls; };

__device__ __forceinline__ Cand decode_cand(
    int b, int n,
    const float* __restrict__ l0, const float* __restrict__ l1,
    const float* __restrict__ l2)
{
  const float* base; int G, lvl, m; float stride;
  if (n < 1083)      { base = l0; G = 19; stride = 32.f; lvl = 0; m = n;        }
  else if (n < 5415) { base = l1; G = 38; stride = 16.f; lvl = 1; m = n - 1083; }
  else               { base = l2; G = 76; stride =  8.f; lvl = 2; m = n - 5415; }
  int GG = G * G;
  int a  = m / GG;
  int r  = m - a * GG;
  int gi = r / G;
  int gj = r - gi * G;
  const float* p = base + ((size_t)(b * 3 + a) * GG + r) * 26;

  float sx  = 1.f / (1.f + expf(-p[0]));
  float sy  = 1.f / (1.f + expf(-p[1]));
  float obj = 1.f / (1.f + expf(-p[4]));
  float loc = 1.f / (1.f + expf(-p[5]));
  float cx = (sx + (float)gj) * stride;
  float cy = (sy + (float)gi) * stride;
  float w = expf(p[2]) * c_anchors[lvl][a][0];  // (anchor/stride)*stride exact (stride = 2^k)
  float h = expf(p[3]) * c_anchors[lvl][a][1];

  float lg[20];
  float maxl = -1e30f; int ci = 0;
  #pragma unroll
  for (int k = 0; k < 20; k++) {
    lg[k] = p[6 + k];
    if (lg[k] > maxl) { maxl = lg[k]; ci = k; }   // first-max tiebreak like argmax
  }
  float sum = 0.f;
  #pragma unroll
  for (int k = 0; k < 20; k++) sum += expf(lg[k] - maxl);
  float conf = 1.0f / sum;                        // max softmax prob

  float x1 = fminf(fmaxf(cx - 0.5f * w, 0.f), 608.f);
  float y1 = fminf(fmaxf(cy - 0.5f * h, 0.f), 608.f);
  float x2 = fminf(fmaxf(cx + 0.5f * w, 0.f), 608.f);
  float y2 = fminf(fmaxf(cy + 0.5f * h, 0.f), 608.f);

  bool valid = (obj >= 0.6f) && (obj * conf >= 0.05f) && (loc >= 0.5f);
  // area >= 608*608*0 is always true
  float score = sqrtf(obj * conf) * sqrtf(loc);

  Cand c;
  c.x1 = x1; c.y1 = y1; c.x2 = x2; c.y2 = y2;
  c.val = valid ? score : NEGF;
  c.cls = ci;
  return c;
}

// -------- Kernel A: decode every anchor, write order-preserving score key --------
__global__ void decode_score_kernel(const float* __restrict__ l0,
                                    const float* __restrict__ l1,
                                    const float* __restrict__ l2)
{
  int idx = blockIdx.x * blockDim.x + threadIdx.x;
  if (idx >= NB * NCAND) return;
  int b = idx / NCAND;
  int n = idx - b * NCAND;
  Cand c = decode_cand(b, n, l0, l1, l2);
  g_keys[idx] = fkey(c.val);
}

// -------- Kernel B: per-image radix-select top-256 (threshold + compaction) --------
__global__ void select_kernel()
{
  int b = blockIdx.x;
  const uint32_t* __restrict__ keys = g_keys + (size_t)b * NCAND;

  __shared__ int hist[256];
  __shared__ uint32_t s_prefix;
  __shared__ int s_remaining, s_above;
  __shared__ int c_gt, c_eq;

  uint32_t prefix = 0, mask = 0;
  int remaining = MCAND;
  int above_total = 0;

  for (int pass = 0; pass < 4; pass++) {
    int shift = 24 - pass * 8;
    hist[threadIdx.x] = 0;
    __syncthreads();
    for (int n = threadIdx.x; n < NCAND; n += 256) {
      uint32_t k = keys[n];
      if ((k & mask) == prefix) atomicAdd(&hist[(k >> shift) & 0xFF], 1);
    }
    __syncthreads();
    if (threadIdx.x == 0) {
      int cum = 0; int d = 255;
      for (; d > 0; d--) {
        if (cum + hist[d] >= remaining) break;
        cum += hist[d];
      }
      s_above     = above_total + cum;        // count strictly greater so far
      s_remaining = remaining - cum;          // in [1, hist[d]]
      s_prefix    = prefix | ((uint32_t)d << shift);
    }
    __syncthreads();
    prefix      = s_prefix;
    remaining   = s_remaining;
    above_total = s_above;
    mask |= (0xFFu << shift);
    __syncthreads();
  }

  uint32_t T  = prefix;            // exact key of the 256th largest
  int cnt_gt  = above_total;       // #keys strictly > T  (< 256)
  int need_eq = MCAND - cnt_gt;    // fill rest with keys == T

  if (threadIdx.x == 0) { c_gt = 0; c_eq = 0; }
  __syncthreads();

  int* sel = g_sel + b * MCAND;
  for (int n = threadIdx.x; n < NCAND; n += 256) {
    uint32_t k = keys[n];
    if (k > T) {
      int p = atomicAdd(&c_gt, 1);
      sel[p] = n;
    } else if (k == T) {
      int p = atomicAdd(&c_eq, 1);
      if (p < need_eq) sel[cnt_gt + p] = n;
    }
  }
}

// -------- Kernel D: per-image candidate decode + class-decomposed soft-NMS + top-8 --------
__global__ void nms_kernel(const float* __restrict__ l0,
                           const float* __restrict__ l1,
                           const float* __restrict__ l2,
                           float* __restrict__ out)
{
  int b = blockIdx.x;
  int t = threadIdx.x;

  __shared__ float sx1[MCAND], sy1[MCAND], sx2[MCAND], sy2[MCAND];
  __shared__ float ss[MCAND], sval[MCAND];
  __shared__ int   scls[MCAND];
  __shared__ unsigned char skept[MCAND];
  __shared__ int ccount[20], cbase[20], cfill[20];
  __shared__ short order[MCAND];
  __shared__ unsigned long long red[MCAND];

  int n = g_sel[b * MCAND + t];
  Cand c = decode_cand(b, n, l0, l1, l2);
  sx1[t] = c.x1; sy1[t] = c.y1; sx2[t] = c.x2; sy2[t] = c.y2;
  sval[t] = c.val;       // original (pre-decay) score; NEG if invalid
  ss[t]   = c.val;       // live NMS score
  scls[t] = c.cls;
  skept[t] = 0;
  if (t < 20) { ccount[t] = 0; cfill[t] = 0; }
  __syncthreads();

  atomicAdd(&ccount[c.cls], 1);
  __syncthreads();
  if (t == 0) {
    int acc = 0;
    for (int k = 0; k < 20; k++) { cbase[k] = acc; acc += ccount[k]; }
  }
  __syncthreads();
  {
    int slot = atomicAdd(&cfill[c.cls], 1);
    order[cbase[c.cls] + slot] = (short)t;
  }
  __syncthreads();

  // Soft-NMS decays are class-local -> decompose into 20 independent runs.
  if (t < 20) {
    int nc = ccount[t];
    int base = cbase[t];
    while (true) {
      float bs = -1e30f; int bi = -1;
      for (int m = 0; m < nc; m++) {
        int i = order[base + m];
        float v = ss[i];
        if (v > bs) { bs = v; bi = i; }
      }
      if (bi < 0 || bs < 0.1f) break;      // NMS_T
      skept[bi] = 1;
      float bx1 = sx1[bi], by1 = sy1[bi], bx2 = sx2[bi], by2 = sy2[bi];
      float a1 = (bx2 - bx1 + 1.f) * (by2 - by1 + 1.f);
      for (int m = 0; m < nc; m++) {
        int i = order[base + m];
        float ix1 = fmaxf(bx1, sx1[i]);
        float iy1 = fmaxf(by1, sy1[i]);
        float ix2 = fminf(bx2, sx2[i]);
        float iy2 = fminf(by2, sy2[i]);
        float inter = fmaxf(ix2 - ix1 + 1.f, 0.f) * fmaxf(iy2 - iy1 + 1.f, 0.f);
        float a2 = (sx2[i] - sx1[i] + 1.f) * (sy2[i] - sy1[i] + 1.f);
        float iou = inter / (a1 + a2 - inter + 1e-16f);
        ss[i] *= expf(-2.0f * iou * iou);  // exp(-iou^2 / 0.5)
      }
      ss[bi] = NEGF;
    }
  }
  __syncthreads();

  // Final: top-8 among kept, ranked by ORIGINAL score, lowest-index tiebreak.
  float fs = skept[t] ? sval[t] : NEGF;
  for (int r = 0; r < 8; r++) {
    uint32_t ou = fkey(fs);
    red[t] = (((unsigned long long)ou) << 32) | (unsigned long long)(uint32_t)(255 - t);
    __syncthreads();
    for (int off = 128; off > 0; off >>= 1) {
      if (t < off) {
        unsigned long long o = red[t + off];
        if (o > red[t]) red[t] = o;
      }
      __syncthreads();
    }
    unsigned long long win = red[0];
    int w = 255 - (int)(win & 0xFFFFFFFFull);
    if (t == w) {
      float* o = out + ((size_t)b * 8 + r) * 6;
      if (fs > -5e8f) {   // NEG/2 cutoff
        o[0] = sx1[t]; o[1] = sy1[t]; o[2] = sx2[t]; o[3] = sy2[t];
        o[4] = fs;     o[5] = (float)scls[t];
      } else {
        o[0] = 0.f; o[1] = 0.f; o[2] = 0.f; o[3] = 0.f; o[4] = 0.f; o[5] = 0.f;
      }
      fs = NEGF;
    }
    __syncthreads();
  }
}

extern "C" void kernel_launch(void* const* d_in, const int* in_sizes, int n_in,
                              void* d_out, int out_size)
{
  // Robust input mapping by element count.
  const float* l0 = nullptr; const float* l1 = nullptr; const float* l2 = nullptr;
  for (int i = 0; i < n_in; i++) {
    if      (in_sizes[i] == 64 * 3 * 19 * 19 * 26) l0 = (const float*)d_in[i];
    else if (in_sizes[i] == 64 * 3 * 38 * 38 * 26) l1 = (const float*)d_in[i];
    else if (in_sizes[i] == 64 * 3 * 76 * 76 * 26) l2 = (const float*)d_in[i];
  }
  float* out = (float*)d_out;

  int total = NB * NCAND;
  decode_score_kernel<<<(total + 255) / 256, 256>>>(l0, l1, l2);
  select_kernel<<<NB, 256>>>();
  nms_kernel<<<NB, 256>>>(l0, l1, l2, out);
}

// round 6
// speedup vs baseline: 3.5675x; 3.5675x over previous
#include <cuda_runtime.h>
#include <cstdint>

#define NB     64
#define NCAND  22743      // 3*(19^2 + 38^2 + 76^2)
#define NCPAD  22744      // padded so per-image key rows are 16B-aligned
#define MCAND  256
#define NEGF   (-1e9f)

__constant__ float c_anchors[3][3][2] = {
  {{116.f, 90.f},{156.f,198.f},{373.f,326.f}},
  {{ 30.f, 61.f},{ 62.f, 45.f},{ 59.f,119.f}},
  {{ 10.f, 13.f},{ 16.f, 30.f},{ 33.f, 23.f}}
};

__device__ __align__(16) uint32_t g_keys[(size_t)NB * NCPAD];
__device__ int g_sel[(size_t)NB * MCAND];

__device__ __forceinline__ uint32_t fkey(float f) {
  uint32_t u = __float_as_uint(f);
  return (u & 0x80000000u) ? ~u : (u | 0x80000000u);
}

struct Cand { float x1, y1, x2, y2, val; int cls; };

__device__ __forceinline__ Cand decode_cand(
    int b, int n,
    const float* __restrict__ l0, const float* __restrict__ l1,
    const float* __restrict__ l2)
{
  const float* base; int G, lvl, m; float stride;
  if (n < 1083)      { base = l0; G = 19; stride = 32.f; lvl = 0; m = n;        }
  else if (n < 5415) { base = l1; G = 38; stride = 16.f; lvl = 1; m = n - 1083; }
  else               { base = l2; G = 76; stride =  8.f; lvl = 2; m = n - 5415; }
  int GG = G * G;
  int a  = m / GG;
  int r  = m - a * GG;
  int gi = r / G;
  int gj = r - gi * G;
  const float* p = base + ((size_t)(b * 3 + a) * GG + r) * 26;

  // 104-byte record is 8B-aligned -> vectorized float2 loads (halves L1 wavefronts)
  const float2* __restrict__ p2 = reinterpret_cast<const float2*>(p);
  float f[26];
  #pragma unroll
  for (int i = 0; i < 13; i++) { float2 v = p2[i]; f[2*i] = v.x; f[2*i+1] = v.y; }

  float sx  = 1.f / (1.f + expf(-f[0]));
  float sy  = 1.f / (1.f + expf(-f[1]));
  float obj = 1.f / (1.f + expf(-f[4]));
  float loc = 1.f / (1.f + expf(-f[5]));
  float cx = (sx + (float)gj) * stride;
  float cy = (sy + (float)gi) * stride;
  float w = expf(f[2]) * c_anchors[lvl][a][0];
  float h = expf(f[3]) * c_anchors[lvl][a][1];

  float maxl = -1e30f; int ci = 0;
  #pragma unroll
  for (int k = 0; k < 20; k++) {
    if (f[6+k] > maxl) { maxl = f[6+k]; ci = k; }
  }
  float sum = 0.f;
  #pragma unroll
  for (int k = 0; k < 20; k++) sum += expf(f[6+k] - maxl);
  float conf = 1.0f / sum;

  float x1 = fminf(fmaxf(cx - 0.5f * w, 0.f), 608.f);
  float y1 = fminf(fmaxf(cy - 0.5f * h, 0.f), 608.f);
  float x2 = fminf(fmaxf(cx + 0.5f * w, 0.f), 608.f);
  float y2 = fminf(fmaxf(cy + 0.5f * h, 0.f), 608.f);

  bool valid = (obj >= 0.6f) && (obj * conf >= 0.05f) && (loc >= 0.5f);
  float score = sqrtf(obj * conf) * sqrtf(loc);

  Cand c;
  c.x1 = x1; c.y1 = y1; c.x2 = x2; c.y2 = y2;
  c.val = valid ? score : NEGF;
  c.cls = ci;
  return c;
}

// -------- Kernel A: decode every anchor, write order-preserving score key --------
__global__ void decode_score_kernel(const float* __restrict__ l0,
                                    const float* __restrict__ l1,
                                    const float* __restrict__ l2)
{
  int idx = blockIdx.x * blockDim.x + threadIdx.x;   // covers NB*NCPAD exactly
  int b = idx / NCPAD;
  int n = idx - b * NCPAD;
  if (n >= NCAND) { g_keys[idx] = 0u; return; }      // pad key, never selected
  Cand c = decode_cand(b, n, l0, l1, l2);
  g_keys[idx] = fkey(c.val);
}

// -------- Kernel B: per-image radix-select top-256, smem-staged, parallel scan ----
__global__ void select_kernel()
{
  int b = blockIdx.x;
  int t = threadIdx.x;

  extern __shared__ uint32_t smem_sel[];
  uint32_t* skeys = smem_sel;                 // NCPAD
  int* hist = (int*)(smem_sel + NCPAD);       // 256
  int* suf  = hist + 256;                     // 256
  __shared__ int s_rem, s_abv, s_d;
  __shared__ int c_gt, c_eq;

  // stage keys once (vectorized; NCPAD/4 = 5686 uint4s)
  {
    const uint4* __restrict__ gk4 = (const uint4*)(g_keys + (size_t)b * NCPAD);
    uint4* sk4 = (uint4*)skeys;
    for (int i = t; i < NCPAD / 4; i += 1024) sk4[i] = gk4[i];
  }
  if (t == 0) { c_gt = 0; c_eq = 0; }
  __syncthreads();

  uint32_t prefix = 0, mask = 0;
  int remaining = MCAND, above = 0;

  #pragma unroll
  for (int pass = 0; pass < 4; pass++) {
    int shift = 24 - pass * 8;
    if (t < 256) hist[t] = 0;
    __syncthreads();
    for (int n = t; n < NCAND; n += 1024) {
      uint32_t k = skeys[n];
      if ((k & mask) == prefix) atomicAdd(&hist[(k >> shift) & 0xFF], 1);
    }
    __syncthreads();
    // suffix sums over bins (Hillis-Steele, high->low)
    if (t < 256) suf[t] = hist[t];
    __syncthreads();
    for (int off = 1; off < 256; off <<= 1) {
      int v = (t < 256 && t + off < 256) ? suf[t + off] : 0;
      __syncthreads();
      if (t < 256) suf[t] += v;
      __syncthreads();
    }
    if (t < 256) {
      int sd  = suf[t];
      int sd1 = (t == 255) ? 0 : suf[t + 1];
      if (sd >= remaining && sd1 < remaining) {
        s_d = t; s_rem = remaining - sd1; s_abv = above + sd1;
      }
    }
    __syncthreads();
    prefix |= ((uint32_t)s_d) << shift;
    remaining = s_rem;
    above     = s_abv;
    mask |= (0xFFu << shift);
    __syncthreads();
  }

  uint32_t T = prefix;           // exact key of the 256th-largest
  int cnt_gt = above;            // strictly greater count (< 256)
  int need_eq = MCAND - cnt_gt;

  int* sel = g_sel + b * MCAND;
  for (int n = t; n < NCAND; n += 1024) {
    uint32_t k = skeys[n];
    if (k > T) {
      sel[atomicAdd(&c_gt, 1)] = n;
    } else if (k == T) {
      int p = atomicAdd(&c_eq, 1);
      if (p < need_eq) sel[cnt_gt + p] = n;
    }
  }
}

// -------- Kernel D: candidate decode + warp-per-class soft-NMS + warp top-8 -------
__global__ void nms_kernel(const float* __restrict__ l0,
                           const float* __restrict__ l1,
                           const float* __restrict__ l2,
                           float* __restrict__ out)
{
  int b = blockIdx.x;
  int t = threadIdx.x;

  __shared__ float sx1[MCAND], sy1[MCAND], sx2[MCAND], sy2[MCAND];
  __shared__ float ss[MCAND], sval[MCAND];
  __shared__ int   scls[MCAND];
  __shared__ unsigned char skept[MCAND];
  __shared__ int ccount[20], cbase[20], cfill[20];
  __shared__ short order[MCAND];

  if (t < 20) { ccount[t] = 0; cfill[t] = 0; }
  __syncthreads();

  int mycls = -1;
  if (t < MCAND) {
    int n = g_sel[b * MCAND + t];
    Cand c = decode_cand(b, n, l0, l1, l2);
    sx1[t] = c.x1; sy1[t] = c.y1; sx2[t] = c.x2; sy2[t] = c.y2;
    sval[t] = c.val;
    ss[t]   = c.val;
    scls[t] = c.cls;
    skept[t] = 0;
    mycls = c.cls;
    atomicAdd(&ccount[mycls], 1);
  }
  __syncthreads();
  if (t == 0) {
    int acc = 0;
    #pragma unroll
    for (int k = 0; k < 20; k++) { cbase[k] = acc; acc += ccount[k]; }
  }
  __syncthreads();
  if (t < MCAND) {
    int slot = atomicAdd(&cfill[mycls], 1);
    order[cbase[mycls] + slot] = (short)t;
  }
  __syncthreads();

  // Class-decomposed soft-NMS: one warp per class.
  int w = t >> 5, l = t & 31;
  if (w < 20) {
    int nc = ccount[w];
    int base = cbase[w];
    const uint32_t thresh = fkey(0.1f);   // NMS_T
    while (true) {
      // warp argmax (lowest-index tiebreak via 255-i in low bits)
      unsigned long long best = 0ull;
      for (int m = l; m < nc; m += 32) {
        int i = order[base + m];
        unsigned long long pk =
            (((unsigned long long)fkey(ss[i])) << 32) | (unsigned)(255 - i);
        if (pk > best) best = pk;
      }
      #pragma unroll
      for (int off = 16; off; off >>= 1) {
        unsigned long long o = __shfl_xor_sync(0xffffffffu, best, off);
        if (o > best) best = o;
      }
      if ((uint32_t)(best >> 32) < thresh) break;
      int bi = 255 - (int)(best & 0xffffffffu);

      float bx1 = sx1[bi], by1 = sy1[bi], bx2 = sx2[bi], by2 = sy2[bi];
      float a1 = (bx2 - bx1 + 1.f) * (by2 - by1 + 1.f);
      __syncwarp();
      for (int m = l; m < nc; m += 32) {
        int i = order[base + m];
        float ix1 = fmaxf(bx1, sx1[i]);
        float iy1 = fmaxf(by1, sy1[i]);
        float ix2 = fminf(bx2, sx2[i]);
        float iy2 = fminf(by2, sy2[i]);
        float inter = fmaxf(ix2 - ix1 + 1.f, 0.f) * fmaxf(iy2 - iy1 + 1.f, 0.f);
        float a2 = (sx2[i] - sx1[i] + 1.f) * (sy2[i] - sy1[i] + 1.f);
        float iou = inter / (a1 + a2 - inter + 1e-16f);
        ss[i] *= expf(-2.0f * iou * iou);   // exp(-iou^2 / sigma), sigma=0.5
      }
      __syncwarp();
      if (l == 0) { skept[bi] = 1; ss[bi] = NEGF; }
      __syncwarp();
    }
  }
  __syncthreads();

  // Top-8 among kept by ORIGINAL score (lowest-index tiebreak) — warp 0 only.
  if (t < 32) {
    float v[8];
    #pragma unroll
    for (int k = 0; k < 8; k++) {
      int j = (k << 5) | t;
      v[k] = skept[j] ? sval[j] : NEGF;
    }
    const uint32_t okkey = fkey(-5e8f);   // NEG/2 cutoff
    for (int r = 0; r < 8; r++) {
      unsigned long long best = 0ull;
      #pragma unroll
      for (int k = 0; k < 8; k++) {
        int j = (k << 5) | t;
        unsigned long long pk =
            (((unsigned long long)fkey(v[k])) << 32) | (unsigned)(255 - j);
        if (pk > best) best = pk;
      }
      #pragma unroll
      for (int off = 16; off; off >>= 1) {
        unsigned long long o = __shfl_xor_sync(0xffffffffu, best, off);
        if (o > best) best = o;
      }
      int jw = 255 - (int)(best & 0xffffffffu);
      uint32_t kw = (uint32_t)(best >> 32);
      if ((jw & 31) == t) {
        float* o = out + ((size_t)b * 8 + r) * 6;
        if (kw > okkey) {
          o[0] = sx1[jw]; o[1] = sy1[jw]; o[2] = sx2[jw]; o[3] = sy2[jw];
          o[4] = sval[jw]; o[5] = (float)scls[jw];
        } else {
          o[0] = 0.f; o[1] = 0.f; o[2] = 0.f; o[3] = 0.f; o[4] = 0.f; o[5] = 0.f;
        }
        v[jw >> 5] = NEGF;
      }
    }
  }
}

extern "C" void kernel_launch(void* const* d_in, const int* in_sizes, int n_in,
                              void* d_out, int out_size)
{
  const float* l0 = nullptr; const float* l1 = nullptr; const float* l2 = nullptr;
  for (int i = 0; i < n_in; i++) {
    if      (in_sizes[i] == 64 * 3 * 19 * 19 * 26) l0 = (const float*)d_in[i];
    else if (in_sizes[i] == 64 * 3 * 38 * 38 * 26) l1 = (const float*)d_in[i];
    else if (in_sizes[i] == 64 * 3 * 76 * 76 * 26) l2 = (const float*)d_in[i];
  }
  float* out = (float*)d_out;

  static bool attr_done = false;
  if (!attr_done) {
    cudaFuncSetAttribute(select_kernel,
                         cudaFuncAttributeMaxDynamicSharedMemorySize, 96 * 1024);
    attr_done = true;
  }

  int total = NB * NCPAD;                        // 1,455,616 = 5686 * 256
  decode_score_kernel<<<total / 256, 256>>>(l0, l1, l2);
  size_t sel_smem = (size_t)(NCPAD + 512) * sizeof(uint32_t);
  select_kernel<<<NB, 1024, sel_smem>>>();
  nms_kernel<<<NB, 640>>>(l0, l1, l2, out);
}